// round 4
// baseline (speedup 1.0000x reference)
#include <cuda_runtime.h>
#include <math.h>

#define Nn 512
#define Bb 8
#define Cc 64
#define Hh 64
#define Tt 16
#define Ll 2
#define Ee 16384
#define NB (Nn*Bb)          /* 4096 rows for gate GEMMs */
#define MAT (NB*Hh)         /* 262144 floats per [N,B,H] matrix */

// ---------------- device scratch (static, no runtime allocation) ----------------
__device__ float g_S[Nn*Nn];          // dense normalized (negated) adjacency, [dst][src]
__device__ float g_deg[Nn];
__device__ float g_dinv[Nn];
__device__ float g_U[(long)Tt*3*MAT]; // Chebyshev basis of x: [t][k][n*B+b][c]
__device__ float g_h[MAT];            // hidden state [n][b][h]
__device__ float g_z[MAT];
__device__ float g_hr[MAT];
__device__ float g_T1[MAT];
__device__ float g_T2[MAT];
__device__ float g_sp[MAT];
__device__ float g_tp[MAT];
__device__ int   g_idx32;             // 1 if edge_index is int32, 0 if int64

// ---------------- dtype probe ----------------
// If edge_index is truly int64 (values in [0,512)), every 64-bit read is small.
// If it is int32, the high word of each 64-bit read is a node id (nonzero w.p.
// ~1-1/512 per entry), so some value >= Nn appears among the first 64 reads.
__global__ void probe_kernel(const void* __restrict__ ei) {
    const long long* p = (const long long*)ei;
    int is64 = 1;
    for (int i = 0; i < 64; i++) {
        long long v = p[i];
        if (v < 0 || v >= (long long)Nn) { is64 = 0; break; }
    }
    g_idx32 = is64 ? 0 : 1;
}

__device__ __forceinline__ int load_idx(const void* ei, long i) {
    if (g_idx32) return ((const int*)ei)[i];
    return (int)(((const long long*)ei)[i]);
}

// ---------------- init / graph build ----------------
__global__ void zero_init_kernel() {
    int i = blockIdx.x * blockDim.x + threadIdx.x;
    if (i < Nn*Nn) g_S[i] = 0.0f;
    if (i < MAT)   g_h[i] = 0.0f;
    if (i < Nn)    g_deg[i] = 0.0f;
}

__global__ void deg_kernel(const void* __restrict__ ei, const float* __restrict__ w) {
    int e = blockIdx.x * blockDim.x + threadIdx.x;
    if (e < Ee) {
        int s = load_idx(ei, e);
        atomicAdd(&g_deg[s], w[e]);
    }
}

__global__ void dinv_kernel() {
    int i = blockIdx.x * blockDim.x + threadIdx.x;
    if (i < Nn) {
        float d = g_deg[i];
        g_dinv[i] = (d > 0.0f) ? rsqrtf(fmaxf(d, 1e-12f)) : 0.0f;
    }
}

__global__ void scatterS_kernel(const void* __restrict__ ei, const float* __restrict__ w) {
    int e = blockIdx.x * blockDim.x + threadIdx.x;
    if (e < Ee) {
        int s = load_idx(ei, e);
        int d = load_idx(ei, (long)Ee + e);
        float nw = -w[e] * g_dinv[s] * g_dinv[d];
        atomicAdd(&g_S[(long)d * Nn + s], nw);
    }
}

// x[b][t][n][c] -> g_U[t][0][n*B+b][c]
__global__ void permute_x_kernel(const float* __restrict__ x) {
    long i = (long)blockIdx.x * blockDim.x + threadIdx.x;
    const long total = (long)Bb * Tt * Nn * Cc;
    if (i < total) {
        int c = (int)(i & 63);
        long r = i >> 6;
        int n = (int)(r % Nn); r /= Nn;
        int t = (int)(r % Tt);
        int b = (int)(r / Tt);
        g_U[((long)(t*3) * NB + (long)n * Bb + b) * Hh + c] = x[i];
    }
}

// ---------------- S-GEMM: O[z] = alpha * S @ X[z] + beta * Y[z] ----------------
// S: [512,512]; X,Y,O: [512 rows, 512 cols] (node-major [N][B*H])
__global__ void sgemm_S(const float* __restrict__ Xb, long xs,
                        const float* __restrict__ Yb, long ys,
                        float* __restrict__ Ob, long os,
                        float alpha, float beta) {
    const float* X = Xb + (long)blockIdx.z * xs;
    const float* Y = Yb ? (Yb + (long)blockIdx.z * ys) : (const float*)0;
    float* O = Ob + (long)blockIdx.z * os;

    __shared__ float As[16][64];  // S tile, transposed: As[k][m]
    __shared__ float Bs[16][64];  // X tile: Bs[k][n]

    int tx = threadIdx.x, ty = threadIdx.y;
    int tid = ty * 16 + tx;
    int mBase = blockIdx.y * 64, nBase = blockIdx.x * 64;

    float acc[4][4];
    #pragma unroll
    for (int i = 0; i < 4; i++)
        #pragma unroll
        for (int j = 0; j < 4; j++) acc[i][j] = 0.0f;

    for (int kk = 0; kk < 512; kk += 16) {
        #pragma unroll
        for (int i = tid; i < 1024; i += 256) {
            int r = i >> 4, c = i & 15;
            As[c][r] = g_S[(long)(mBase + r) * 512 + kk + c];
        }
        #pragma unroll
        for (int i = tid; i < 1024; i += 256) {
            int k = i >> 6, c = i & 63;
            Bs[k][c] = X[(long)(kk + k) * 512 + nBase + c];
        }
        __syncthreads();
        #pragma unroll
        for (int k = 0; k < 16; k++) {
            float a0 = As[k][ty*4+0], a1 = As[k][ty*4+1], a2 = As[k][ty*4+2], a3 = As[k][ty*4+3];
            float b0 = Bs[k][tx*4+0], b1 = Bs[k][tx*4+1], b2 = Bs[k][tx*4+2], b3 = Bs[k][tx*4+3];
            acc[0][0] += a0*b0; acc[0][1] += a0*b1; acc[0][2] += a0*b2; acc[0][3] += a0*b3;
            acc[1][0] += a1*b0; acc[1][1] += a1*b1; acc[1][2] += a1*b2; acc[1][3] += a1*b3;
            acc[2][0] += a2*b0; acc[2][1] += a2*b1; acc[2][2] += a2*b2; acc[2][3] += a2*b3;
            acc[3][0] += a3*b0; acc[3][1] += a3*b1; acc[3][2] += a3*b2; acc[3][3] += a3*b3;
        }
        __syncthreads();
    }

    #pragma unroll
    for (int i = 0; i < 4; i++) {
        #pragma unroll
        for (int j = 0; j < 4; j++) {
            long r = mBase + ty*4 + i, c = nBase + tx*4 + j;
            float v = alpha * acc[i][j];
            if (beta != 0.0f) v += beta * Y[r * 512 + c];
            O[r * 512 + c] = v;
        }
    }
}

// ---------------- Gate GEMM: out = epilogue( sum_p A_p @ W_p + b1 + b2 ) ----------------
// A_p: [4096, 64] row-major; W_p: [64, 64] row-major. One 64-row block per CTA, full 64 cols.
struct GateArgs {
    const float* A[6];
    const float* W[6];
    const float* bias1;
    const float* bias2;
    const float* hin;
    const float* zin;
    float* out;
    int npairs;
    int mode;   // 0: sigmoid(z)  1: h*sigmoid(r)->hr  2: GRU update -> h  3: linear
};

__global__ void gate_gemm(GateArgs ga) {
    __shared__ float As[16][64]; // As[k][m]
    __shared__ float Ws[16][64]; // Ws[k][n]

    int tx = threadIdx.x, ty = threadIdx.y;
    int tid = ty * 16 + tx;
    int mBase = blockIdx.x * 64;

    float acc[4][4];
    #pragma unroll
    for (int i = 0; i < 4; i++)
        #pragma unroll
        for (int j = 0; j < 4; j++) acc[i][j] = 0.0f;

    for (int p = 0; p < ga.npairs; p++) {
        const float* A = ga.A[p];
        const float* W = ga.W[p];
        for (int kk = 0; kk < 64; kk += 16) {
            #pragma unroll
            for (int i = tid; i < 1024; i += 256) {
                int r = i >> 4, c = i & 15;
                As[c][r] = A[(long)(mBase + r) * 64 + kk + c];
            }
            #pragma unroll
            for (int i = tid; i < 1024; i += 256) {
                int k = i >> 6, c = i & 63;
                Ws[k][c] = W[(long)(kk + k) * 64 + c];
            }
            __syncthreads();
            #pragma unroll
            for (int k = 0; k < 16; k++) {
                float a0 = As[k][ty*4+0], a1 = As[k][ty*4+1], a2 = As[k][ty*4+2], a3 = As[k][ty*4+3];
                float b0 = Ws[k][tx*4+0], b1 = Ws[k][tx*4+1], b2 = Ws[k][tx*4+2], b3 = Ws[k][tx*4+3];
                acc[0][0] += a0*b0; acc[0][1] += a0*b1; acc[0][2] += a0*b2; acc[0][3] += a0*b3;
                acc[1][0] += a1*b0; acc[1][1] += a1*b1; acc[1][2] += a1*b2; acc[1][3] += a1*b3;
                acc[2][0] += a2*b0; acc[2][1] += a2*b1; acc[2][2] += a2*b2; acc[2][3] += a2*b3;
                acc[3][0] += a3*b0; acc[3][1] += a3*b1; acc[3][2] += a3*b2; acc[3][3] += a3*b3;
            }
            __syncthreads();
        }
    }

    #pragma unroll
    for (int i = 0; i < 4; i++) {
        #pragma unroll
        for (int j = 0; j < 4; j++) {
            int r = mBase + ty*4 + i;
            int c = tx*4 + j;
            long idx = (long)r * 64 + c;
            float v = acc[i][j];
            if (ga.bias1) v += ga.bias1[c];
            if (ga.bias2) v += ga.bias2[c];
            if (ga.mode == 0) {
                ga.out[idx] = 1.0f / (1.0f + expf(-v));
            } else if (ga.mode == 1) {
                ga.out[idx] = ga.hin[idx] * (1.0f / (1.0f + expf(-v)));
            } else if (ga.mode == 2) {
                float zt = ga.zin[idx];
                ga.out[idx] = zt * ga.hin[idx] + (1.0f - zt) * tanhf(v);
            } else {
                ga.out[idx] = v;
            }
        }
    }
}

// ---------------- all-pairs link predictor ----------------
// logits[b][s][t] = sum_h relu(sp[s][b][h] + tp[t][b][h] + b1[h]) * W2[h] + b2
__global__ void predict_kernel(const float* __restrict__ b1,
                               const float* __restrict__ W2,
                               const float* __restrict__ b2,
                               float* __restrict__ out) {
    __shared__ float sps[32][65];
    __shared__ float tps[32][65];
    __shared__ float b1s[64];
    __shared__ float w2s[64];

    int tx = threadIdx.x, ty = threadIdx.y;
    int tid = ty * 32 + tx;
    int b = blockIdx.z;
    int sBase = blockIdx.y * 32, tBase = blockIdx.x * 32;

    for (int i = tid; i < 2048; i += 1024) {
        int r = i >> 6, c = i & 63;
        sps[r][c] = g_sp[((long)(sBase + r) * Bb + b) * Hh + c];
        tps[r][c] = g_tp[((long)(tBase + r) * Bb + b) * Hh + c];
    }
    if (tid < 64) { b1s[tid] = b1[tid]; w2s[tid] = W2[tid]; }
    __syncthreads();

    float acc = b2[0];
    #pragma unroll
    for (int hh = 0; hh < 64; hh++) {
        float v = sps[ty][hh] + tps[tx][hh] + b1s[hh];
        acc += fmaxf(v, 0.0f) * w2s[hh];
    }
    out[((long)b * Nn + (sBase + ty)) * Nn + (tBase + tx)] = acc;
}

// ---------------- host-side orchestration ----------------
extern "C" void kernel_launch(void* const* d_in, const int* in_sizes, int n_in,
                              void* d_out, int out_size) {
    const float* x   = (const float*)d_in[0];
    const float* ew  = (const float*)d_in[1];
    const float* Wx  = (const float*)d_in[2];
    const float* bx  = (const float*)d_in[3];
    const float* Wh  = (const float*)d_in[4];
    const float* bh  = (const float*)d_in[5];
    const float* W1  = (const float*)d_in[6];
    const float* b1  = (const float*)d_in[7];
    const float* W2  = (const float*)d_in[8];
    const float* b2  = (const float*)d_in[9];
    const void*  ei  = d_in[10];          // int32 or int64 — probed at runtime
    float* out = (float*)d_out;

    float *U, *h, *z, *hr, *T1, *T2, *sp, *tp;
    cudaGetSymbolAddress((void**)&U,  g_U);
    cudaGetSymbolAddress((void**)&h,  g_h);
    cudaGetSymbolAddress((void**)&z,  g_z);
    cudaGetSymbolAddress((void**)&hr, g_hr);
    cudaGetSymbolAddress((void**)&T1, g_T1);
    cudaGetSymbolAddress((void**)&T2, g_T2);
    cudaGetSymbolAddress((void**)&sp, g_sp);
    cudaGetSymbolAddress((void**)&tp, g_tp);

    // 1) init + graph build
    probe_kernel<<<1, 1>>>(ei);
    zero_init_kernel<<<(Nn*Nn + 255)/256, 256>>>();
    deg_kernel<<<(Ee + 255)/256, 256>>>(ei, ew);
    dinv_kernel<<<(Nn + 255)/256, 256>>>();
    scatterS_kernel<<<(Ee + 255)/256, 256>>>(ei, ew);

    // 2) Chebyshev basis of x for all timesteps: U0 (permute), U1 = S U0, U2 = 2 S U1 - U0
    {
        long total = (long)Bb * Tt * Nn * Cc;
        permute_x_kernel<<<(int)((total + 255)/256), 256>>>(x);
        dim3 gs(8, 8, Tt), bs(16, 16);
        sgemm_S<<<gs, bs>>>(U + 0,   (long)3*MAT, (const float*)0, 0, U + MAT,   (long)3*MAT, 1.0f,  0.0f);
        sgemm_S<<<gs, bs>>>(U + MAT, (long)3*MAT, U + 0, (long)3*MAT, U + 2*MAT, (long)3*MAT, 2.0f, -1.0f);
    }

    dim3 gs1(8, 8, 1), bs(16, 16);

    // 3) recurrent GRU over T x L
    for (int t = 0; t < Tt; t++) {
        const float* Ut0 = U + ((long)(t*3 + 0)) * MAT;
        const float* Ut1 = U + ((long)(t*3 + 1)) * MAT;
        const float* Ut2 = U + ((long)(t*3 + 2)) * MAT;
        for (int l = 0; l < Ll; l++) {
            // h-side Chebyshev basis: T1 = S h, T2 = 2 S T1 - h
            sgemm_S<<<gs1, bs>>>(h, 0, (const float*)0, 0, T1, 0, 1.0f, 0.0f);
            sgemm_S<<<gs1, bs>>>(T1, 0, h, 0, T2, 0, 2.0f, -1.0f);

            // gate z (mode 0) and gate r -> hr (mode 1)
            for (int g = 0; g < 2; g++) {
                GateArgs ga;
                ga.A[0] = Ut0; ga.A[1] = Ut1; ga.A[2] = Ut2;
                ga.A[3] = h;   ga.A[4] = T1;  ga.A[5] = T2;
                for (int k = 0; k < 3; k++) {
                    ga.W[k]     = Wx + (long)(((l*3 + g)*3 + k)) * (Cc*Hh);
                    ga.W[3 + k] = Wh + (long)(((l*3 + g)*3 + k)) * (Hh*Hh);
                }
                ga.bias1 = bx + (long)(l*3 + g) * Hh;
                ga.bias2 = bh + (long)(l*3 + g) * Hh;
                ga.hin = h; ga.zin = z;
                ga.npairs = 6;
                ga.mode = g;            // 0 -> z, 1 -> hr
                ga.out = (g == 0) ? z : hr;
                gate_gemm<<<NB/64, bs>>>(ga);
            }

            // hr-side Chebyshev basis (reuse T1/T2)
            sgemm_S<<<gs1, bs>>>(hr, 0, (const float*)0, 0, T1, 0, 1.0f, 0.0f);
            sgemm_S<<<gs1, bs>>>(T1, 0, hr, 0, T2, 0, 2.0f, -1.0f);

            // gate h_tilde + GRU update (writes h in place)
            {
                GateArgs ga;
                ga.A[0] = Ut0; ga.A[1] = Ut1; ga.A[2] = Ut2;
                ga.A[3] = hr;  ga.A[4] = T1;  ga.A[5] = T2;
                for (int k = 0; k < 3; k++) {
                    ga.W[k]     = Wx + (long)(((l*3 + 2)*3 + k)) * (Cc*Hh);
                    ga.W[3 + k] = Wh + (long)(((l*3 + 2)*3 + k)) * (Hh*Hh);
                }
                ga.bias1 = bx + (long)(l*3 + 2) * Hh;
                ga.bias2 = bh + (long)(l*3 + 2) * Hh;
                ga.hin = h; ga.zin = z;
                ga.npairs = 6;
                ga.mode = 2;
                ga.out = h;
                gate_gemm<<<NB/64, bs>>>(ga);
            }
        }
    }

    // 4) link predictor projections: sp = h @ W1_top, tp = h @ W1_bot
    {
        GateArgs ga;
        ga.A[0] = h; ga.W[0] = W1;
        ga.bias1 = 0; ga.bias2 = 0; ga.hin = 0; ga.zin = 0;
        ga.npairs = 1; ga.mode = 3;
        ga.out = sp;
        gate_gemm<<<NB/64, bs>>>(ga);
        ga.W[0] = W1 + 64*64;
        ga.out = tp;
        gate_gemm<<<NB/64, bs>>>(ga);
    }

    // 5) all-pairs logits
    {
        dim3 g(Nn/32, Nn/32, Bb), t(32, 32);
        predict_kernel<<<g, t>>>(b1, W2, b2, out);
    }
}

// round 5
// speedup vs baseline: 3.0573x; 3.0573x over previous
#include <cuda_runtime.h>
#include <math.h>

#define Nn 512
#define Bb 8
#define Cc 64
#define Hh 64
#define Tt 16
#define Ll 2
#define Ee 16384
#define NB (Nn*Bb)          /* 4096 rows for gate GEMMs */
#define MAT (NB*Hh)         /* 262144 floats per [N,B,H] matrix */

// ---------------- device scratch (static, no runtime allocation) ----------------
__device__ float g_S[Nn*Nn];            // dense normalized (negated) adjacency, [dst][src]
__device__ float g_deg[Nn];
__device__ float g_dinv[Nn];
__device__ float g_U[(long)Tt*3*MAT];   // Chebyshev basis of x: [t][k][n*B+b][c]
__device__ float g_Xc[(long)Tt*Ll*3*MAT]; // precomputed x-side gate pre-activations (+biases)
__device__ float g_h[MAT];              // hidden state [n][b][h]
__device__ float g_z[MAT];
__device__ float g_hr[MAT];
__device__ float g_T1[MAT];
__device__ float g_T2[MAT];
__device__ float g_sp[MAT];
__device__ float g_tp[MAT];
__device__ int   g_idx32;               // 1 if edge_index is int32, 0 if int64

// ---------------- dtype probe ----------------
__global__ void probe_kernel(const void* __restrict__ ei) {
    const long long* p = (const long long*)ei;
    int is64 = 1;
    for (int i = 0; i < 64; i++) {
        long long v = p[i];
        if (v < 0 || v >= (long long)Nn) { is64 = 0; break; }
    }
    g_idx32 = is64 ? 0 : 1;
}

__device__ __forceinline__ int load_idx(const void* ei, long i) {
    if (g_idx32) return ((const int*)ei)[i];
    return (int)(((const long long*)ei)[i]);
}

// ---------------- init / graph build ----------------
__global__ void zero_init_kernel() {
    int i = blockIdx.x * blockDim.x + threadIdx.x;
    if (i < Nn*Nn) g_S[i] = 0.0f;
    if (i < MAT)   g_h[i] = 0.0f;
    if (i < Nn)    g_deg[i] = 0.0f;
}

__global__ void deg_kernel(const void* __restrict__ ei, const float* __restrict__ w) {
    int e = blockIdx.x * blockDim.x + threadIdx.x;
    if (e < Ee) atomicAdd(&g_deg[load_idx(ei, e)], w[e]);
}

__global__ void dinv_kernel() {
    int i = blockIdx.x * blockDim.x + threadIdx.x;
    if (i < Nn) {
        float d = g_deg[i];
        g_dinv[i] = (d > 0.0f) ? rsqrtf(fmaxf(d, 1e-12f)) : 0.0f;
    }
}

__global__ void scatterS_kernel(const void* __restrict__ ei, const float* __restrict__ w) {
    int e = blockIdx.x * blockDim.x + threadIdx.x;
    if (e < Ee) {
        int s = load_idx(ei, e);
        int d = load_idx(ei, (long)Ee + e);
        atomicAdd(&g_S[(long)d * Nn + s], -w[e] * g_dinv[s] * g_dinv[d]);
    }
}

// x[b][t][n][c] -> g_U[t][0][n*B+b][c]
__global__ void permute_x_kernel(const float* __restrict__ x) {
    long i = (long)blockIdx.x * blockDim.x + threadIdx.x;
    const long total = (long)Bb * Tt * Nn * Cc;
    if (i < total) {
        int c = (int)(i & 63);
        long r = i >> 6;
        int n = (int)(r % Nn); r /= Nn;
        int t = (int)(r % Tt);
        int b = (int)(r / Tt);
        g_U[((long)(t*3) * NB + (long)n * Bb + b) * Hh + c] = x[i];
    }
}

// ============ S-GEMM v2: O[z] = alpha * S @ X[z] + beta * Y[z] ============
// S: [512,512]; X,Y,O: [512,512] fp32 row-major. Tile 32(M)x64(N), K-tile 32,
// double-buffered smem, float4 ldg/lds. grid (8, 16, batch), block 256.
__global__ __launch_bounds__(256) void sgemm_S(
        const float* __restrict__ Xb, long xs,
        const float* __restrict__ Yb, long ys,
        float* __restrict__ Ob, long os,
        float alpha, float beta) {
    const float* X = Xb + (long)blockIdx.z * xs;
    const float* Y = Yb ? (Yb + (long)blockIdx.z * ys) : (const float*)0;
    float* O = Ob + (long)blockIdx.z * os;

    __shared__ float As[2][32][34];   // As[buf][k][m] (transposed S tile)
    __shared__ float Bs[2][32][64];   // Bs[buf][k][n]

    int tid = threadIdx.x;
    int tx = tid & 15;                // n: 4 cols each -> 64
    int ty = tid >> 4;                // m: 2 rows each -> 32
    int mBase = blockIdx.y * 32, nBase = blockIdx.x * 64;

    // load indices
    int lm  = tid >> 3;               // 0..31 : m row for As
    int lk4 = (tid & 7) << 2;         // 0,4,..,28 : k group for As
    int bk  = tid >> 4;               // 0..15 : k row for Bs
    int bn4 = (tid & 15) << 2;        // n group for Bs

    float4 a_reg, b_reg0, b_reg1;

    // prologue: tile 0
    a_reg  = *(const float4*)&g_S[(long)(mBase + lm) * 512 + lk4];
    b_reg0 = *(const float4*)&X[(long)bk * 512 + nBase + bn4];
    b_reg1 = *(const float4*)&X[(long)(16 + bk) * 512 + nBase + bn4];
    As[0][lk4+0][lm] = a_reg.x; As[0][lk4+1][lm] = a_reg.y;
    As[0][lk4+2][lm] = a_reg.z; As[0][lk4+3][lm] = a_reg.w;
    *(float4*)&Bs[0][bk][bn4] = b_reg0;
    *(float4*)&Bs[0][bk+16][bn4] = b_reg1;
    __syncthreads();

    float acc[2][4];
    #pragma unroll
    for (int i = 0; i < 2; i++)
        #pragma unroll
        for (int j = 0; j < 4; j++) acc[i][j] = 0.0f;

    for (int t = 0; t < 16; t++) {
        int cur = t & 1, nxt = cur ^ 1;
        if (t < 15) {
            int kk = (t + 1) * 32;
            a_reg  = *(const float4*)&g_S[(long)(mBase + lm) * 512 + kk + lk4];
            b_reg0 = *(const float4*)&X[(long)(kk + bk) * 512 + nBase + bn4];
            b_reg1 = *(const float4*)&X[(long)(kk + 16 + bk) * 512 + nBase + bn4];
        }
        #pragma unroll
        for (int k = 0; k < 32; k++) {
            float2 a = *(float2*)&As[cur][k][ty * 2];
            float4 b = *(float4*)&Bs[cur][k][tx * 4];
            acc[0][0] += a.x * b.x; acc[0][1] += a.x * b.y;
            acc[0][2] += a.x * b.z; acc[0][3] += a.x * b.w;
            acc[1][0] += a.y * b.x; acc[1][1] += a.y * b.y;
            acc[1][2] += a.y * b.z; acc[1][3] += a.y * b.w;
        }
        if (t < 15) {
            As[nxt][lk4+0][lm] = a_reg.x; As[nxt][lk4+1][lm] = a_reg.y;
            As[nxt][lk4+2][lm] = a_reg.z; As[nxt][lk4+3][lm] = a_reg.w;
            *(float4*)&Bs[nxt][bk][bn4] = b_reg0;
            *(float4*)&Bs[nxt][bk+16][bn4] = b_reg1;
        }
        __syncthreads();
    }

    #pragma unroll
    for (int i = 0; i < 2; i++) {
        long r = mBase + ty * 2 + i;
        long off = r * 512 + nBase + tx * 4;
        float4 v;
        v.x = alpha * acc[i][0]; v.y = alpha * acc[i][1];
        v.z = alpha * acc[i][2]; v.w = alpha * acc[i][3];
        if (Y) {
            float4 y = *(const float4*)&Y[off];
            v.x += beta * y.x; v.y += beta * y.y; v.z += beta * y.z; v.w += beta * y.w;
        }
        *(float4*)&O[off] = v;
    }
}

// ============ Xc precompute: Xc[t][l][g] = sum_k U[t][k] @ Wx[l][g][k] + bx + bh ============
// grid (128, 6, 16): x = M-tile(32 rows), y = l*3+g, z = t. block 256.
__global__ __launch_bounds__(256) void xc_kernel(
        const float* __restrict__ Wx, const float* __restrict__ bx,
        const float* __restrict__ bh) {
    __shared__ float As[2][32][34];
    __shared__ float Bs[2][32][64];

    int tid = threadIdx.x;
    int tx = tid & 15, ty = tid >> 4;
    int mBase = blockIdx.x * 32;
    int lg = blockIdx.y;              // l*3+g
    int t  = blockIdx.z;
    int l = lg / 3, g = lg % 3;

    const float* A0 = g_U + (long)(t*3 + 0) * MAT;
    const float* A1 = g_U + (long)(t*3 + 1) * MAT;
    const float* A2 = g_U + (long)(t*3 + 2) * MAT;
    const float* Aps[3] = {A0, A1, A2};
    const float* Wbase = Wx + (long)lg * 3 * (Cc*Hh);

    int lm  = tid >> 3;
    int lk4 = (tid & 7) << 2;
    int bk  = tid >> 4;
    int bn4 = (tid & 15) << 2;

    float4 a_reg, b_reg0, b_reg1;

    // prologue: tile 0 (source 0, kk 0)
    a_reg  = *(const float4*)&Aps[0][(long)(mBase + lm) * 64 + lk4];
    b_reg0 = *(const float4*)&Wbase[(long)bk * 64 + bn4];
    b_reg1 = *(const float4*)&Wbase[(long)(16 + bk) * 64 + bn4];
    As[0][lk4+0][lm] = a_reg.x; As[0][lk4+1][lm] = a_reg.y;
    As[0][lk4+2][lm] = a_reg.z; As[0][lk4+3][lm] = a_reg.w;
    *(float4*)&Bs[0][bk][bn4] = b_reg0;
    *(float4*)&Bs[0][bk+16][bn4] = b_reg1;
    __syncthreads();

    float acc[2][4];
    #pragma unroll
    for (int i = 0; i < 2; i++)
        #pragma unroll
        for (int j = 0; j < 4; j++) acc[i][j] = 0.0f;

    for (int tile = 0; tile < 6; tile++) {
        int cur = tile & 1, nxt = cur ^ 1;
        if (tile < 5) {
            int p  = (tile + 1) >> 1;
            int kk = ((tile + 1) & 1) * 32;
            const float* A = Aps[p];
            const float* W = Wbase + (long)p * (Cc*Hh);
            a_reg  = *(const float4*)&A[(long)(mBase + lm) * 64 + kk + lk4];
            b_reg0 = *(const float4*)&W[(long)(kk + bk) * 64 + bn4];
            b_reg1 = *(const float4*)&W[(long)(kk + 16 + bk) * 64 + bn4];
        }
        #pragma unroll
        for (int k = 0; k < 32; k++) {
            float2 a = *(float2*)&As[cur][k][ty * 2];
            float4 b = *(float4*)&Bs[cur][k][tx * 4];
            acc[0][0] += a.x * b.x; acc[0][1] += a.x * b.y;
            acc[0][2] += a.x * b.z; acc[0][3] += a.x * b.w;
            acc[1][0] += a.y * b.x; acc[1][1] += a.y * b.y;
            acc[1][2] += a.y * b.z; acc[1][3] += a.y * b.w;
        }
        if (tile < 5) {
            As[nxt][lk4+0][lm] = a_reg.x; As[nxt][lk4+1][lm] = a_reg.y;
            As[nxt][lk4+2][lm] = a_reg.z; As[nxt][lk4+3][lm] = a_reg.w;
            *(float4*)&Bs[nxt][bk][bn4] = b_reg0;
            *(float4*)&Bs[nxt][bk+16][bn4] = b_reg1;
        }
        __syncthreads();
    }

    float* out = g_Xc + ((long)(t*Ll + l) * 3 + g) * MAT;
    int c = tx * 4;
    float bsum0 = bx[lg*Hh + c+0] + bh[lg*Hh + c+0];
    float bsum1 = bx[lg*Hh + c+1] + bh[lg*Hh + c+1];
    float bsum2 = bx[lg*Hh + c+2] + bh[lg*Hh + c+2];
    float bsum3 = bx[lg*Hh + c+3] + bh[lg*Hh + c+3];
    #pragma unroll
    for (int i = 0; i < 2; i++) {
        long r = mBase + ty * 2 + i;
        float4 v;
        v.x = acc[i][0] + bsum0; v.y = acc[i][1] + bsum1;
        v.z = acc[i][2] + bsum2; v.w = acc[i][3] + bsum3;
        *(float4*)&out[r * 64 + c] = v;
    }
}

// ============ Gate GEMM: h-side K=192 (A0,T1,T2) + Xc, fused epilogue ============
// grid (128, ngates). gate g = gbase + blockIdx.y:
//   g==0: g_z  = sigmoid(v)
//   g==1: g_hr = g_h * sigmoid(v)
//   g==2: g_h  = z*h + (1-z)*tanh(v)
__global__ __launch_bounds__(256) void gate_kernel(
        const float* __restrict__ A0,       // h (for z/r) or hr (for h~)
        const float* __restrict__ Wl,       // Wh + l*3*3*64*64
        const float* __restrict__ Xc_tl,    // g_Xc + (t*L+l)*3*MAT
        int gbase) {
    __shared__ float As[2][32][34];
    __shared__ float Bs[2][32][64];

    int tid = threadIdx.x;
    int tx = tid & 15, ty = tid >> 4;
    int mBase = blockIdx.x * 32;
    int g = gbase + blockIdx.y;

    const float* Aps[3] = {A0, g_T1, g_T2};
    const float* Wg = Wl + (long)g * 3 * (Hh*Hh);

    int lm  = tid >> 3;
    int lk4 = (tid & 7) << 2;
    int bk  = tid >> 4;
    int bn4 = (tid & 15) << 2;

    float4 a_reg, b_reg0, b_reg1;

    a_reg  = *(const float4*)&Aps[0][(long)(mBase + lm) * 64 + lk4];
    b_reg0 = *(const float4*)&Wg[(long)bk * 64 + bn4];
    b_reg1 = *(const float4*)&Wg[(long)(16 + bk) * 64 + bn4];
    As[0][lk4+0][lm] = a_reg.x; As[0][lk4+1][lm] = a_reg.y;
    As[0][lk4+2][lm] = a_reg.z; As[0][lk4+3][lm] = a_reg.w;
    *(float4*)&Bs[0][bk][bn4] = b_reg0;
    *(float4*)&Bs[0][bk+16][bn4] = b_reg1;
    __syncthreads();

    float acc[2][4];
    #pragma unroll
    for (int i = 0; i < 2; i++)
        #pragma unroll
        for (int j = 0; j < 4; j++) acc[i][j] = 0.0f;

    for (int tile = 0; tile < 6; tile++) {
        int cur = tile & 1, nxt = cur ^ 1;
        if (tile < 5) {
            int p  = (tile + 1) >> 1;
            int kk = ((tile + 1) & 1) * 32;
            const float* A = Aps[p];
            const float* W = Wg + (long)p * (Hh*Hh);
            a_reg  = *(const float4*)&A[(long)(mBase + lm) * 64 + kk + lk4];
            b_reg0 = *(const float4*)&W[(long)(kk + bk) * 64 + bn4];
            b_reg1 = *(const float4*)&W[(long)(kk + 16 + bk) * 64 + bn4];
        }
        #pragma unroll
        for (int k = 0; k < 32; k++) {
            float2 a = *(float2*)&As[cur][k][ty * 2];
            float4 b = *(float4*)&Bs[cur][k][tx * 4];
            acc[0][0] += a.x * b.x; acc[0][1] += a.x * b.y;
            acc[0][2] += a.x * b.z; acc[0][3] += a.x * b.w;
            acc[1][0] += a.y * b.x; acc[1][1] += a.y * b.y;
            acc[1][2] += a.y * b.z; acc[1][3] += a.y * b.w;
        }
        if (tile < 5) {
            As[nxt][lk4+0][lm] = a_reg.x; As[nxt][lk4+1][lm] = a_reg.y;
            As[nxt][lk4+2][lm] = a_reg.z; As[nxt][lk4+3][lm] = a_reg.w;
            *(float4*)&Bs[nxt][bk][bn4] = b_reg0;
            *(float4*)&Bs[nxt][bk+16][bn4] = b_reg1;
        }
        __syncthreads();
    }

    const float* Xc = Xc_tl + (long)g * MAT;
    int c = tx * 4;
    #pragma unroll
    for (int i = 0; i < 2; i++) {
        long r = mBase + ty * 2 + i;
        long off = r * 64 + c;
        float4 xc = *(const float4*)&Xc[off];
        float v0 = acc[i][0] + xc.x, v1 = acc[i][1] + xc.y;
        float v2 = acc[i][2] + xc.z, v3 = acc[i][3] + xc.w;
        if (g == 0) {
            float4 o;
            o.x = 1.0f / (1.0f + expf(-v0)); o.y = 1.0f / (1.0f + expf(-v1));
            o.z = 1.0f / (1.0f + expf(-v2)); o.w = 1.0f / (1.0f + expf(-v3));
            *(float4*)&g_z[off] = o;
        } else if (g == 1) {
            float4 hv = *(const float4*)&g_h[off];
            float4 o;
            o.x = hv.x / (1.0f + expf(-v0)); o.y = hv.y / (1.0f + expf(-v1));
            o.z = hv.z / (1.0f + expf(-v2)); o.w = hv.w / (1.0f + expf(-v3));
            *(float4*)&g_hr[off] = o;
        } else {
            float4 hv = *(const float4*)&g_h[off];
            float4 zv = *(const float4*)&g_z[off];
            float4 o;
            o.x = zv.x * hv.x + (1.0f - zv.x) * tanhf(v0);
            o.y = zv.y * hv.y + (1.0f - zv.y) * tanhf(v1);
            o.z = zv.z * hv.z + (1.0f - zv.z) * tanhf(v2);
            o.w = zv.w * hv.w + (1.0f - zv.w) * tanhf(v3);
            *(float4*)&g_h[off] = o;
        }
    }
}

// ============ sp/tp projections: grid (128, 2) ============
__global__ __launch_bounds__(256) void spt_kernel(const float* __restrict__ W1) {
    __shared__ float As[2][32][34];
    __shared__ float Bs[2][32][64];

    int tid = threadIdx.x;
    int tx = tid & 15, ty = tid >> 4;
    int mBase = blockIdx.x * 32;
    const float* W = W1 + (long)blockIdx.y * (Hh*Hh);
    float* out = blockIdx.y ? g_tp : g_sp;

    int lm  = tid >> 3;
    int lk4 = (tid & 7) << 2;
    int bk  = tid >> 4;
    int bn4 = (tid & 15) << 2;

    float4 a_reg, b_reg0, b_reg1;

    a_reg  = *(const float4*)&g_h[(long)(mBase + lm) * 64 + lk4];
    b_reg0 = *(const float4*)&W[(long)bk * 64 + bn4];
    b_reg1 = *(const float4*)&W[(long)(16 + bk) * 64 + bn4];
    As[0][lk4+0][lm] = a_reg.x; As[0][lk4+1][lm] = a_reg.y;
    As[0][lk4+2][lm] = a_reg.z; As[0][lk4+3][lm] = a_reg.w;
    *(float4*)&Bs[0][bk][bn4] = b_reg0;
    *(float4*)&Bs[0][bk+16][bn4] = b_reg1;
    __syncthreads();

    float acc[2][4];
    #pragma unroll
    for (int i = 0; i < 2; i++)
        #pragma unroll
        for (int j = 0; j < 4; j++) acc[i][j] = 0.0f;

    for (int tile = 0; tile < 2; tile++) {
        int cur = tile & 1, nxt = cur ^ 1;
        if (tile < 1) {
            int kk = 32;
            a_reg  = *(const float4*)&g_h[(long)(mBase + lm) * 64 + kk + lk4];
            b_reg0 = *(const float4*)&W[(long)(kk + bk) * 64 + bn4];
            b_reg1 = *(const float4*)&W[(long)(kk + 16 + bk) * 64 + bn4];
        }
        #pragma unroll
        for (int k = 0; k < 32; k++) {
            float2 a = *(float2*)&As[cur][k][ty * 2];
            float4 b = *(float4*)&Bs[cur][k][tx * 4];
            acc[0][0] += a.x * b.x; acc[0][1] += a.x * b.y;
            acc[0][2] += a.x * b.z; acc[0][3] += a.x * b.w;
            acc[1][0] += a.y * b.x; acc[1][1] += a.y * b.y;
            acc[1][2] += a.y * b.z; acc[1][3] += a.y * b.w;
        }
        if (tile < 1) {
            As[nxt][lk4+0][lm] = a_reg.x; As[nxt][lk4+1][lm] = a_reg.y;
            As[nxt][lk4+2][lm] = a_reg.z; As[nxt][lk4+3][lm] = a_reg.w;
            *(float4*)&Bs[nxt][bk][bn4] = b_reg0;
            *(float4*)&Bs[nxt][bk+16][bn4] = b_reg1;
        }
        __syncthreads();
    }

    #pragma unroll
    for (int i = 0; i < 2; i++) {
        long r = mBase + ty * 2 + i;
        float4 v; v.x = acc[i][0]; v.y = acc[i][1]; v.z = acc[i][2]; v.w = acc[i][3];
        *(float4*)&out[r * 64 + tx * 4] = v;
    }
}

// ---------------- all-pairs link predictor ----------------
__global__ void predict_kernel(const float* __restrict__ b1,
                               const float* __restrict__ W2,
                               const float* __restrict__ b2,
                               float* __restrict__ out) {
    __shared__ float sps[32][65];
    __shared__ float tps[32][65];
    __shared__ float b1s[64];
    __shared__ float w2s[64];

    int tx = threadIdx.x, ty = threadIdx.y;
    int tid = ty * 32 + tx;
    int b = blockIdx.z;
    int sBase = blockIdx.y * 32, tBase = blockIdx.x * 32;

    for (int i = tid; i < 2048; i += 1024) {
        int r = i >> 6, c = i & 63;
        sps[r][c] = g_sp[((long)(sBase + r) * Bb + b) * Hh + c];
        tps[r][c] = g_tp[((long)(tBase + r) * Bb + b) * Hh + c];
    }
    if (tid < 64) { b1s[tid] = b1[tid]; w2s[tid] = W2[tid]; }
    __syncthreads();

    float acc = b2[0];
    #pragma unroll
    for (int hh = 0; hh < 64; hh++) {
        float v = sps[ty][hh] + tps[tx][hh] + b1s[hh];
        acc += fmaxf(v, 0.0f) * w2s[hh];
    }
    out[((long)b * Nn + (sBase + ty)) * Nn + (tBase + tx)] = acc;
}

// ---------------- host-side orchestration ----------------
extern "C" void kernel_launch(void* const* d_in, const int* in_sizes, int n_in,
                              void* d_out, int out_size) {
    const float* x   = (const float*)d_in[0];
    const float* ew  = (const float*)d_in[1];
    const float* Wx  = (const float*)d_in[2];
    const float* bx  = (const float*)d_in[3];
    const float* Wh  = (const float*)d_in[4];
    const float* bh  = (const float*)d_in[5];
    const float* W1  = (const float*)d_in[6];
    const float* b1  = (const float*)d_in[7];
    const float* W2  = (const float*)d_in[8];
    const float* b2  = (const float*)d_in[9];
    const void*  ei  = d_in[10];
    float* out = (float*)d_out;

    float *U, *h, *hr, *T1, *T2;
    cudaGetSymbolAddress((void**)&U,  g_U);
    cudaGetSymbolAddress((void**)&h,  g_h);
    cudaGetSymbolAddress((void**)&hr, g_hr);
    cudaGetSymbolAddress((void**)&T1, g_T1);
    cudaGetSymbolAddress((void**)&T2, g_T2);
    float* Xc;
    cudaGetSymbolAddress((void**)&Xc, g_Xc);

    // 1) init + graph build
    probe_kernel<<<1, 1>>>(ei);
    zero_init_kernel<<<(Nn*Nn + 255)/256, 256>>>();
    deg_kernel<<<(Ee + 255)/256, 256>>>(ei, ew);
    dinv_kernel<<<(Nn + 255)/256, 256>>>();
    scatterS_kernel<<<(Ee + 255)/256, 256>>>(ei, ew);

    // 2) Chebyshev basis of x: U0 (permute), U1 = S U0, U2 = 2 S U1 - U0 (all t batched)
    {
        long total = (long)Bb * Tt * Nn * Cc;
        permute_x_kernel<<<(int)((total + 255)/256), 256>>>(x);
        dim3 gs(8, 16, Tt);
        sgemm_S<<<gs, 256>>>(U + 0,   (long)3*MAT, (const float*)0, 0, U + MAT,   (long)3*MAT, 1.0f,  0.0f);
        sgemm_S<<<gs, 256>>>(U + MAT, (long)3*MAT, U + 0, (long)3*MAT, U + 2*MAT, (long)3*MAT, 2.0f, -1.0f);
    }

    // 3) precompute x-side gate pre-activations for all (t, l, g) — one wide launch
    xc_kernel<<<dim3(128, 6, Tt), 256>>>(Wx, bx, bh);

    // 4) recurrent GRU over T x L
    dim3 gs1(8, 16, 1);
    for (int t = 0; t < Tt; t++) {
        for (int l = 0; l < Ll; l++) {
            const float* Wl    = Wh + (long)l * 3 * 3 * (Hh*Hh);
            const float* Xc_tl = Xc + ((long)(t*Ll + l) * 3) * MAT;

            // h-side Chebyshev basis: T1 = S h, T2 = 2 S T1 - h
            sgemm_S<<<gs1, 256>>>(h, 0, (const float*)0, 0, T1, 0, 1.0f, 0.0f);
            sgemm_S<<<gs1, 256>>>(T1, 0, h, 0, T2, 0, 2.0f, -1.0f);

            // fused z + r gates (r epilogue produces hr directly)
            gate_kernel<<<dim3(128, 2), 256>>>(h, Wl, Xc_tl, 0);

            // hr-side Chebyshev basis
            sgemm_S<<<gs1, 256>>>(hr, 0, (const float*)0, 0, T1, 0, 1.0f, 0.0f);
            sgemm_S<<<gs1, 256>>>(T1, 0, hr, 0, T2, 0, 2.0f, -1.0f);

            // h~ gate + GRU update (writes h in place)
            gate_kernel<<<dim3(128, 1), 256>>>(hr, Wl, Xc_tl, 2);
        }
    }

    // 5) link predictor projections (one launch, both halves)
    spt_kernel<<<dim3(128, 2), 256>>>(W1);

    // 6) all-pairs logits
    {
        dim3 g(Nn/32, Nn/32, Bb), t(32, 32);
        predict_kernel<<<g, t>>>(b1, W2, b2, out);
    }
}

// round 6
// speedup vs baseline: 3.0880x; 1.0100x over previous
#include <cuda_runtime.h>
#include <math.h>

#define Nn 512
#define Bb 8
#define Cc 64
#define Hh 64
#define Tt 16
#define Ll 2
#define Ee 16384
#define NB (Nn*Bb)          /* 4096 rows for gate GEMMs */
#define MAT (NB*Hh)         /* 262144 floats per [N,B,H] matrix */

typedef unsigned long long u64;

// ---------------- device scratch (static, no runtime allocation) ----------------
__device__ float g_S[Nn*Nn];            // dense normalized (negated) adjacency, [dst][src]
__device__ float g_S2[Nn*Nn];           // S @ S
__device__ float g_deg[Nn];
__device__ float g_dinv[Nn];
__device__ float g_U[(long)Tt*3*MAT];   // Chebyshev basis of x: [t][k][n*B+b][c]
__device__ float g_Xc[(long)Tt*Ll*3*MAT]; // precomputed x-side gate pre-activations (+biases)
__device__ float g_h[MAT];              // hidden state [n][b][h]
__device__ float g_z[MAT];
__device__ float g_hr[MAT];
__device__ float g_T1[MAT];
__device__ float g_T2[MAT];
__device__ float g_sp[MAT];
__device__ float g_tp[MAT];
__device__ int   g_idx32;               // 1 if edge_index is int32, 0 if int64

// ---------------- f32x2 helpers ----------------
__device__ __forceinline__ u64 ffma2(u64 a, u64 b, u64 c) {
    u64 d;
    asm("fma.rn.f32x2 %0, %1, %2, %3;" : "=l"(d) : "l"(a), "l"(b), "l"(c));
    return d;
}
__device__ __forceinline__ u64 splat2(float x) {
    u64 r;
    asm("mov.b64 %0, {%1, %1};" : "=l"(r) : "r"(__float_as_uint(x)));
    return r;
}
__device__ __forceinline__ float2 u2f(u64 v) {
    float2 f;
    asm("mov.b64 {%0, %1}, %2;" : "=f"(f.x), "=f"(f.y) : "l"(v));
    return f;
}

// ---------------- dtype probe ----------------
__global__ void probe_kernel(const void* __restrict__ ei) {
    const long long* p = (const long long*)ei;
    int is64 = 1;
    for (int i = 0; i < 64; i++) {
        long long v = p[i];
        if (v < 0 || v >= (long long)Nn) { is64 = 0; break; }
    }
    g_idx32 = is64 ? 0 : 1;
}

__device__ __forceinline__ int load_idx(const void* ei, long i) {
    if (g_idx32) return ((const int*)ei)[i];
    return (int)(((const long long*)ei)[i]);
}

// ---------------- init / graph build ----------------
__global__ void zero_init_kernel() {
    int i = blockIdx.x * blockDim.x + threadIdx.x;
    if (i < Nn*Nn) g_S[i] = 0.0f;
    if (i < MAT)   g_h[i] = 0.0f;
    if (i < Nn)    g_deg[i] = 0.0f;
}

__global__ void deg_kernel(const void* __restrict__ ei, const float* __restrict__ w) {
    int e = blockIdx.x * blockDim.x + threadIdx.x;
    if (e < Ee) atomicAdd(&g_deg[load_idx(ei, e)], w[e]);
}

__global__ void dinv_kernel() {
    int i = blockIdx.x * blockDim.x + threadIdx.x;
    if (i < Nn) {
        float d = g_deg[i];
        g_dinv[i] = (d > 0.0f) ? rsqrtf(fmaxf(d, 1e-12f)) : 0.0f;
    }
}

__global__ void scatterS_kernel(const void* __restrict__ ei, const float* __restrict__ w) {
    int e = blockIdx.x * blockDim.x + threadIdx.x;
    if (e < Ee) {
        int s = load_idx(ei, e);
        int d = load_idx(ei, (long)Ee + e);
        atomicAdd(&g_S[(long)d * Nn + s], -w[e] * g_dinv[s] * g_dinv[d]);
    }
}

// x[b][t][n][c] -> g_U[t][0][n*B+b][c]
__global__ void permute_x_kernel(const float* __restrict__ x) {
    long i = (long)blockIdx.x * blockDim.x + threadIdx.x;
    const long total = (long)Bb * Tt * Nn * Cc;
    if (i < total) {
        int c = (int)(i & 63);
        long r = i >> 6;
        int n = (int)(r % Nn); r /= Nn;
        int t = (int)(r % Tt);
        int b = (int)(r / Tt);
        g_U[((long)(t*3) * NB + (long)n * Bb + b) * Hh + c] = x[i];
    }
}

// ============ K=512 GEMM core (f32x2): O = alpha * M @ X + beta * Y ============
// M: [512,512]; X,Y,O: [512,512]. Tile 32(M)x64(N), K-tile 32, double-buffered.
// As2 holds splatted {a,a} pairs so the FFMA2 A-operand needs no pack MOVs.
// block 256; caller supplies blockIdx.x (n-tile), blockIdx.y (m-tile).
__device__ __forceinline__ void gemm512_core(
        const float* __restrict__ M, const float* __restrict__ X,
        const float* __restrict__ Y, float* __restrict__ O,
        float alpha, float beta) {
    __shared__ __align__(16) u64   As2[2][32][34];  // [buf][k][m] splatted
    __shared__ __align__(16) float Bs[2][32][64];   // [buf][k][n]

    int tid = threadIdx.x;
    int tx = tid & 15;                // n: 4 cols
    int ty = tid >> 4;                // m: 2 rows
    int mBase = blockIdx.y * 32, nBase = blockIdx.x * 64;

    int lm  = tid >> 3;               // 0..31 : m row for As
    int lk4 = (tid & 7) << 2;         // k group for As
    int bk  = tid >> 4;               // k row for Bs
    int bn4 = (tid & 15) << 2;        // n group for Bs

    float4 a_reg, b_reg0, b_reg1;

    a_reg  = *(const float4*)&M[(long)(mBase + lm) * 512 + lk4];
    b_reg0 = *(const float4*)&X[(long)bk * 512 + nBase + bn4];
    b_reg1 = *(const float4*)&X[(long)(16 + bk) * 512 + nBase + bn4];
    As2[0][lk4+0][lm] = splat2(a_reg.x); As2[0][lk4+1][lm] = splat2(a_reg.y);
    As2[0][lk4+2][lm] = splat2(a_reg.z); As2[0][lk4+3][lm] = splat2(a_reg.w);
    *(float4*)&Bs[0][bk][bn4] = b_reg0;
    *(float4*)&Bs[0][bk+16][bn4] = b_reg1;
    __syncthreads();

    u64 acc[2][2] = {{0ull, 0ull}, {0ull, 0ull}};

    for (int t = 0; t < 16; t++) {
        int cur = t & 1, nxt = cur ^ 1;
        if (t < 15) {
            int kk = (t + 1) * 32;
            a_reg  = *(const float4*)&M[(long)(mBase + lm) * 512 + kk + lk4];
            b_reg0 = *(const float4*)&X[(long)(kk + bk) * 512 + nBase + bn4];
            b_reg1 = *(const float4*)&X[(long)(kk + 16 + bk) * 512 + nBase + bn4];
        }
        #pragma unroll
        for (int k = 0; k < 32; k++) {
            ulonglong2 a2 = *(const ulonglong2*)&As2[cur][k][ty * 2];
            ulonglong2 b2 = *(const ulonglong2*)&Bs[cur][k][tx * 4];
            acc[0][0] = ffma2(a2.x, b2.x, acc[0][0]);
            acc[0][1] = ffma2(a2.x, b2.y, acc[0][1]);
            acc[1][0] = ffma2(a2.y, b2.x, acc[1][0]);
            acc[1][1] = ffma2(a2.y, b2.y, acc[1][1]);
        }
        if (t < 15) {
            As2[nxt][lk4+0][lm] = splat2(a_reg.x); As2[nxt][lk4+1][lm] = splat2(a_reg.y);
            As2[nxt][lk4+2][lm] = splat2(a_reg.z); As2[nxt][lk4+3][lm] = splat2(a_reg.w);
            *(float4*)&Bs[nxt][bk][bn4] = b_reg0;
            *(float4*)&Bs[nxt][bk+16][bn4] = b_reg1;
        }
        __syncthreads();
    }

    #pragma unroll
    for (int i = 0; i < 2; i++) {
        long r = mBase + ty * 2 + i;
        long off = r * 512 + nBase + tx * 4;
        float2 lo = u2f(acc[i][0]), hi = u2f(acc[i][1]);
        float4 v;
        v.x = alpha * lo.x; v.y = alpha * lo.y;
        v.z = alpha * hi.x; v.w = alpha * hi.y;
        if (Y) {
            float4 y = *(const float4*)&Y[off];
            v.x += beta * y.x; v.y += beta * y.y; v.z += beta * y.z; v.w += beta * y.w;
        }
        *(float4*)&O[off] = v;
    }
}

// S2 = S @ S. grid (8, 16)
__global__ __launch_bounds__(256) void s2_kernel() {
    gemm512_core(g_S, g_S, (const float*)0, g_S2, 1.0f, 0.0f);
}

// T1 = S @ X (z=0);  T2 = 2 * S2 @ X - X (z=1). grid (8, 16, 2)
__global__ __launch_bounds__(256) void t1t2_kernel(const float* __restrict__ X) {
    if (blockIdx.z == 0) gemm512_core(g_S,  X, (const float*)0, g_T1, 1.0f,  0.0f);
    else                 gemm512_core(g_S2, X, X,               g_T2, 2.0f, -1.0f);
}

// x-basis: for t = z>>1:  w=0: U1 = S U0;  w=1: U2 = 2 S2 U0 - U0. grid (8, 16, 32)
__global__ __launch_bounds__(256) void basis_kernel() {
    int t = blockIdx.z >> 1, w = blockIdx.z & 1;
    const float* U0 = g_U + (long)(t*3) * MAT;
    if (w == 0) gemm512_core(g_S,  U0, (const float*)0, g_U + (long)(t*3+1)*MAT, 1.0f,  0.0f);
    else        gemm512_core(g_S2, U0, U0,              g_U + (long)(t*3+2)*MAT, 2.0f, -1.0f);
}

// ============ small GEMM core (f32x2): acc += sum over ntiles of A_p tile @ W tile ============
// A matrices [4096 x 64] row-major; W logically [ntiles*32 rows x 64], row = p*64 + kk + k
// tile i: p = i>>1, kk = (i&1)*32.  Tile 32(M)x64(N).
__device__ __forceinline__ void mm64_core(
        const float* __restrict__ A0, const float* __restrict__ A1,
        const float* __restrict__ A2, const float* __restrict__ W,
        int ntiles, int mBase, u64 acc[2][2]) {
    __shared__ __align__(16) u64   As2[2][32][34];
    __shared__ __align__(16) float Bs[2][32][64];

    int tid = threadIdx.x;
    int tx = tid & 15, ty = tid >> 4;
    int lm  = tid >> 3;
    int lk4 = (tid & 7) << 2;
    int bk  = tid >> 4;
    int bn4 = (tid & 15) << 2;

    const float* Aps[3] = {A0, A1, A2};

    float4 a_reg, b_reg0, b_reg1;

    a_reg  = *(const float4*)&A0[(long)(mBase + lm) * 64 + lk4];
    b_reg0 = *(const float4*)&W[(long)bk * 64 + bn4];
    b_reg1 = *(const float4*)&W[(long)(16 + bk) * 64 + bn4];
    As2[0][lk4+0][lm] = splat2(a_reg.x); As2[0][lk4+1][lm] = splat2(a_reg.y);
    As2[0][lk4+2][lm] = splat2(a_reg.z); As2[0][lk4+3][lm] = splat2(a_reg.w);
    *(float4*)&Bs[0][bk][bn4] = b_reg0;
    *(float4*)&Bs[0][bk+16][bn4] = b_reg1;
    __syncthreads();

    for (int tile = 0; tile < ntiles; tile++) {
        int cur = tile & 1, nxt = cur ^ 1;
        if (tile + 1 < ntiles) {
            int p  = (tile + 1) >> 1;
            int kk = ((tile + 1) & 1) * 32;
            const float* A = Aps[p];
            int wr = p * 64 + kk;
            a_reg  = *(const float4*)&A[(long)(mBase + lm) * 64 + kk + lk4];
            b_reg0 = *(const float4*)&W[(long)(wr + bk) * 64 + bn4];
            b_reg1 = *(const float4*)&W[(long)(wr + 16 + bk) * 64 + bn4];
        }
        #pragma unroll
        for (int k = 0; k < 32; k++) {
            ulonglong2 a2 = *(const ulonglong2*)&As2[cur][k][ty * 2];
            ulonglong2 b2 = *(const ulonglong2*)&Bs[cur][k][tx * 4];
            acc[0][0] = ffma2(a2.x, b2.x, acc[0][0]);
            acc[0][1] = ffma2(a2.x, b2.y, acc[0][1]);
            acc[1][0] = ffma2(a2.y, b2.x, acc[1][0]);
            acc[1][1] = ffma2(a2.y, b2.y, acc[1][1]);
        }
        if (tile + 1 < ntiles) {
            As2[nxt][lk4+0][lm] = splat2(a_reg.x); As2[nxt][lk4+1][lm] = splat2(a_reg.y);
            As2[nxt][lk4+2][lm] = splat2(a_reg.z); As2[nxt][lk4+3][lm] = splat2(a_reg.w);
            *(float4*)&Bs[nxt][bk][bn4] = b_reg0;
            *(float4*)&Bs[nxt][bk+16][bn4] = b_reg1;
        }
        __syncthreads();
    }
}

// ============ Xc precompute: Xc[t][l][g] = sum_k U[t][k] @ Wx[l][g][k] + bx + bh ============
// grid (128, 6, 16)
__global__ __launch_bounds__(256) void xc_kernel(
        const float* __restrict__ Wx, const float* __restrict__ bx,
        const float* __restrict__ bh) {
    int tid = threadIdx.x;
    int tx = tid & 15, ty = tid >> 4;
    int mBase = blockIdx.x * 32;
    int lg = blockIdx.y;
    int t  = blockIdx.z;
    int l = lg / 3;

    const float* A0 = g_U + (long)(t*3 + 0) * MAT;
    const float* A1 = g_U + (long)(t*3 + 1) * MAT;
    const float* A2 = g_U + (long)(t*3 + 2) * MAT;
    const float* Wbase = Wx + (long)lg * 3 * (Cc*Hh);

    u64 acc[2][2] = {{0ull, 0ull}, {0ull, 0ull}};
    mm64_core(A0, A1, A2, Wbase, 6, mBase, acc);

    float* out = g_Xc + ((long)(t*Ll + l) * 3 + (lg % 3)) * MAT;
    int c = tx * 4;
    float b0 = bx[lg*Hh + c+0] + bh[lg*Hh + c+0];
    float b1v = bx[lg*Hh + c+1] + bh[lg*Hh + c+1];
    float b2v = bx[lg*Hh + c+2] + bh[lg*Hh + c+2];
    float b3 = bx[lg*Hh + c+3] + bh[lg*Hh + c+3];
    #pragma unroll
    for (int i = 0; i < 2; i++) {
        long r = mBase + ty * 2 + i;
        float2 lo = u2f(acc[i][0]), hi = u2f(acc[i][1]);
        float4 v;
        v.x = lo.x + b0; v.y = lo.y + b1v; v.z = hi.x + b2v; v.w = hi.y + b3;
        *(float4*)&out[r * 64 + c] = v;
    }
}

// ============ Gate GEMM: K=192 (A0,T1,T2) vs Wh, fused GRU epilogues ============
// grid (128, ngates). gate g = gbase + blockIdx.y:
//   g==0: g_z  = sigmoid(v);  g==1: g_hr = g_h * sigmoid(v);  g==2: g_h = z*h+(1-z)*tanh(v)
__global__ __launch_bounds__(256) void gate_kernel(
        const float* __restrict__ A0, const float* __restrict__ Wl,
        const float* __restrict__ Xc_tl, int gbase) {
    int tid = threadIdx.x;
    int tx = tid & 15, ty = tid >> 4;
    int mBase = blockIdx.x * 32;
    int g = gbase + blockIdx.y;
    const float* Wg = Wl + (long)g * 3 * (Hh*Hh);

    u64 acc[2][2] = {{0ull, 0ull}, {0ull, 0ull}};
    mm64_core(A0, g_T1, g_T2, Wg, 6, mBase, acc);

    const float* Xc = Xc_tl + (long)g * MAT;
    int c = tx * 4;
    #pragma unroll
    for (int i = 0; i < 2; i++) {
        long r = mBase + ty * 2 + i;
        long off = r * 64 + c;
        float4 xc = *(const float4*)&Xc[off];
        float2 lo = u2f(acc[i][0]), hi = u2f(acc[i][1]);
        float v0 = lo.x + xc.x, v1 = lo.y + xc.y;
        float v2 = hi.x + xc.z, v3 = hi.y + xc.w;
        if (g == 0) {
            float4 o;
            o.x = 1.0f / (1.0f + expf(-v0)); o.y = 1.0f / (1.0f + expf(-v1));
            o.z = 1.0f / (1.0f + expf(-v2)); o.w = 1.0f / (1.0f + expf(-v3));
            *(float4*)&g_z[off] = o;
        } else if (g == 1) {
            float4 hv = *(const float4*)&g_h[off];
            float4 o;
            o.x = hv.x / (1.0f + expf(-v0)); o.y = hv.y / (1.0f + expf(-v1));
            o.z = hv.z / (1.0f + expf(-v2)); o.w = hv.w / (1.0f + expf(-v3));
            *(float4*)&g_hr[off] = o;
        } else {
            float4 hv = *(const float4*)&g_h[off];
            float4 zv = *(const float4*)&g_z[off];
            float4 o;
            o.x = zv.x * hv.x + (1.0f - zv.x) * tanhf(v0);
            o.y = zv.y * hv.y + (1.0f - zv.y) * tanhf(v1);
            o.z = zv.z * hv.z + (1.0f - zv.z) * tanhf(v2);
            o.w = zv.w * hv.w + (1.0f - zv.w) * tanhf(v3);
            *(float4*)&g_h[off] = o;
        }
    }
}

// ============ sp/tp projections: grid (128, 2) ============
__global__ __launch_bounds__(256) void spt_kernel(const float* __restrict__ W1) {
    int tid = threadIdx.x;
    int tx = tid & 15, ty = tid >> 4;
    int mBase = blockIdx.x * 32;
    const float* W = W1 + (long)blockIdx.y * (Hh*Hh);
    float* out = blockIdx.y ? g_tp : g_sp;

    u64 acc[2][2] = {{0ull, 0ull}, {0ull, 0ull}};
    mm64_core(g_h, g_h, g_h, W, 2, mBase, acc);   // 2 tiles -> only A0, W rows 0..63

    #pragma unroll
    for (int i = 0; i < 2; i++) {
        long r = mBase + ty * 2 + i;
        float2 lo = u2f(acc[i][0]), hi = u2f(acc[i][1]);
        float4 v; v.x = lo.x; v.y = lo.y; v.z = hi.x; v.w = hi.y;
        *(float4*)&out[r * 64 + tx * 4] = v;
    }
}

// ---------------- all-pairs link predictor ----------------
__global__ void predict_kernel(const float* __restrict__ b1,
                               const float* __restrict__ W2,
                               const float* __restrict__ b2,
                               float* __restrict__ out) {
    __shared__ float sps[32][65];   // sp + b1 pre-added
    __shared__ float tps[32][65];
    __shared__ float w2s[64];

    int tx = threadIdx.x, ty = threadIdx.y;
    int tid = ty * 32 + tx;
    int b = blockIdx.z;
    int sBase = blockIdx.y * 32, tBase = blockIdx.x * 32;

    for (int i = tid; i < 2048; i += 1024) {
        int r = i >> 6, c = i & 63;
        sps[r][c] = g_sp[((long)(sBase + r) * Bb + b) * Hh + c] + b1[c];
        tps[r][c] = g_tp[((long)(tBase + r) * Bb + b) * Hh + c];
    }
    if (tid < 64) w2s[tid] = W2[tid];
    __syncthreads();

    float acc = b2[0];
    #pragma unroll
    for (int hh = 0; hh < 64; hh++) {
        float v = sps[ty][hh] + tps[tx][hh];
        acc += fmaxf(v, 0.0f) * w2s[hh];
    }
    out[((long)b * Nn + (sBase + ty)) * Nn + (tBase + tx)] = acc;
}

// ---------------- host-side orchestration ----------------
extern "C" void kernel_launch(void* const* d_in, const int* in_sizes, int n_in,
                              void* d_out, int out_size) {
    const float* x   = (const float*)d_in[0];
    const float* ew  = (const float*)d_in[1];
    const float* Wx  = (const float*)d_in[2];
    const float* bx  = (const float*)d_in[3];
    const float* Wh  = (const float*)d_in[4];
    const float* bh  = (const float*)d_in[5];
    const float* W1  = (const float*)d_in[6];
    const float* b1  = (const float*)d_in[7];
    const float* W2  = (const float*)d_in[8];
    const float* b2  = (const float*)d_in[9];
    const void*  ei  = d_in[10];
    float* out = (float*)d_out;

    float *h, *hr, *Xc;
    cudaGetSymbolAddress((void**)&h,  g_h);
    cudaGetSymbolAddress((void**)&hr, g_hr);
    cudaGetSymbolAddress((void**)&Xc, g_Xc);

    // 1) init + graph build
    probe_kernel<<<1, 1>>>(ei);
    zero_init_kernel<<<(Nn*Nn + 255)/256, 256>>>();
    deg_kernel<<<(Ee + 255)/256, 256>>>(ei, ew);
    dinv_kernel<<<(Nn + 255)/256, 256>>>();
    scatterS_kernel<<<(Ee + 255)/256, 256>>>(ei, ew);

    // 2) S2 = S @ S
    s2_kernel<<<dim3(8, 16), 256>>>();

    // 3) Chebyshev basis of x, all t in one launch (U1 and U2 independent via S2)
    {
        long total = (long)Bb * Tt * Nn * Cc;
        permute_x_kernel<<<(int)((total + 255)/256), 256>>>(x);
        basis_kernel<<<dim3(8, 16, 2*Tt), 256>>>();
    }

    // 4) precompute x-side gate pre-activations for all (t, l, g)
    xc_kernel<<<dim3(128, 6, Tt), 256>>>(Wx, bx, bh);

    // 5) recurrent GRU over T x L — 4 launches per cell
    for (int t = 0; t < Tt; t++) {
        for (int l = 0; l < Ll; l++) {
            const float* Wl    = Wh + (long)l * 3 * 3 * (Hh*Hh);
            const float* Xc_tl = Xc + ((long)(t*Ll + l) * 3) * MAT;

            t1t2_kernel<<<dim3(8, 16, 2), 256>>>(h);               // T1=S h, T2=2 S2 h - h
            gate_kernel<<<dim3(128, 2), 256>>>(h, Wl, Xc_tl, 0);   // z and r->hr
            t1t2_kernel<<<dim3(8, 16, 2), 256>>>(hr);              // T1=S hr, T2=2 S2 hr - hr
            gate_kernel<<<dim3(128, 1), 256>>>(hr, Wl, Xc_tl, 2);  // h~ + GRU update
        }
    }

    // 6) link predictor projections
    spt_kernel<<<dim3(128, 2), 256>>>(W1);

    // 7) all-pairs logits
    {
        dim3 g(Nn/32, Nn/32, Bb), tb(32, 32);
        predict_kernel<<<g, tb>>>(b1, W2, b2, out);
    }
}